// round 4
// baseline (speedup 1.0000x reference)
#include <cuda_runtime.h>
#include <cuda_fp16.h>
#include <cstdint>

#define BATCH 2048
#define D0 256
#define D1 256
#define D2 256
#define D3 128

// Scratch (device globals: allocation-free per harness rules)
__device__ __half g_We0h[D1 * D0];
__device__ __half g_We1h[D2 * D1];
__device__ float  g_We2[D3 * D2];
__device__ float  g_h1[BATCH * D1];
__device__ float  g_h2[BATCH * D2];

__device__ __forceinline__ __half2 tanh2_fast(__half2 a) {
    unsigned int u = *reinterpret_cast<unsigned int*>(&a);
    unsigned int y;
    asm("tanh.approx.f16x2 %0, %1;" : "=r"(y) : "r"(u));
    return *reinterpret_cast<__half2*>(&y);
}

__device__ __forceinline__ float atom_apply(float w, int idx) {
    float v = w;                       // identity
    if (idx == 1)      v = sinf(w);
    else if (idx == 2) v = tanhf(w);
    else if (idx == 3) v = w * w;
    return v;
}

// Precompute effective weights We = atom(W, idx). Layers 0/1 stored f16
// (consumed by the f16x2 tanh path); layer 2 stays fp32 (plain GEMM).
__global__ void prep_we_kernel(const float* __restrict__ W0, const int* __restrict__ f0,
                               const float* __restrict__ W1, const int* __restrict__ f1,
                               const float* __restrict__ W2, const int* __restrict__ f2) {
    const int n01 = D1 * D0;           // 65536 (same for layer1)
    const int n2  = D3 * D2;           // 32768
    const int stride = gridDim.x * blockDim.x;
    for (int t = blockIdx.x * blockDim.x + threadIdx.x; t < n01; t += stride) {
        g_We0h[t] = __float2half_rn(atom_apply(W0[t], f0[t]));
        g_We1h[t] = __float2half_rn(atom_apply(W1[t], f1[t]));
    }
    for (int t = blockIdx.x * blockDim.x + threadIdx.x; t < n2; t += stride) {
        g_We2[t] = atom_apply(W2[t], f2[t]);
    }
}

// Hidden layer: h_out[b,o] = sum_i tanh(h[b,i]*We[o,i]) + bias[o]
// f16x2 path: 2 tanh per MUFU op. fp32 accumulation (HADD2 depth 1 only).
// Block (32,8): tx->32 outputs, ty->8 batches.
template <int IN>
__global__ __launch_bounds__(256) void layer_tanh_kernel(
    const float* __restrict__ h_in,     // [BATCH, IN] fp32
    const __half* __restrict__ We,      // [OUT, IN] f16
    const float* __restrict__ bias,     // [OUT]
    float* __restrict__ h_out,          // [BATCH, OUT] fp32
    int OUT) {
    constexpr int I4 = IN / 4;
    __shared__ uint2 We_s[I4 * 32];     // [i4][o]: 4 halfs per entry; lanes->consecutive 8B, conflict-free
    __shared__ uint2 h_s[8][I4];        // [b][i4]: 4 halfs, warp-uniform broadcast reads

    const int tx = threadIdx.x;
    const int ty = threadIdx.y;
    const int tid = ty * 32 + tx;
    const int o0 = blockIdx.x * 32;
    const int b0 = blockIdx.y * 8;

    // Stage We tile (32 rows x IN), transposed. Gmem reads coalesced over i4.
    const uint2* Wg = reinterpret_cast<const uint2*>(We + o0 * IN);
    for (int idx = tid; idx < 32 * I4; idx += 256) {
        int o = idx / I4, i4 = idx - o * I4;
        We_s[i4 * 32 + o] = Wg[o * I4 + i4];
    }
    // Stage h tile (8 rows), fp32 -> f16 on the fly.
    const float4* Hg = reinterpret_cast<const float4*>(h_in + b0 * IN);
    for (int idx = tid; idx < 8 * I4; idx += 256) {
        int b = idx / I4, i4 = idx - b * I4;
        float4 v = Hg[b * I4 + i4];
        __half2 p0 = __floats2half2_rn(v.x, v.y);
        __half2 p1 = __floats2half2_rn(v.z, v.w);
        uint2 u;
        u.x = *reinterpret_cast<unsigned int*>(&p0);
        u.y = *reinterpret_cast<unsigned int*>(&p1);
        h_s[b][i4] = u;
    }
    __syncthreads();

    const uint2* wc = &We_s[tx];
    const uint2* hr = h_s[ty];
    float acc0 = 0.f, acc1 = 0.f;
#pragma unroll 8
    for (int i4 = 0; i4 < I4; i4++) {
        uint2 w = wc[i4 * 32];
        uint2 hh = hr[i4];
        __half2 w0 = *reinterpret_cast<__half2*>(&w.x);
        __half2 w1 = *reinterpret_cast<__half2*>(&w.y);
        __half2 h0 = *reinterpret_cast<__half2*>(&hh.x);
        __half2 h1 = *reinterpret_cast<__half2*>(&hh.y);
        __half2 t0 = tanh2_fast(__hmul2(h0, w0));
        __half2 t1 = tanh2_fast(__hmul2(h1, w1));
        __half2 s = __hadd2(t0, t1);       // depth-1 f16 add only
        float2 f = __half22float2(s);
        acc0 += f.x;                       // fp32 accumulation
        acc1 += f.y;
    }
    h_out[(b0 + ty) * OUT + o0 + tx] = acc0 + acc1 + bias[o0 + tx];
}

// Last layer (identity): plain fp32 GEMM with register tiling.
// Block (32,8): 32 outputs x 16 batches, each thread 2 batches.
// float4 smem reads: 3 LDS.128 per 8 FFMA -> near FMA-bound.
__global__ __launch_bounds__(256) void layer_lin_kernel(
    const float* __restrict__ h_in,     // [BATCH, 256]
    const float* __restrict__ We,       // [OUT, 256]
    const float* __restrict__ bias,     // [OUT]
    float* __restrict__ out,            // [BATCH, OUT]
    int OUT) {
    constexpr int IN = 256, I4 = IN / 4;
    __shared__ float4 We_s[I4 * 32];    // [i4][o]  32KB
    __shared__ float4 h_s[16][I4];      //          16KB (48KB total, static limit)

    const int tx = threadIdx.x;
    const int ty = threadIdx.y;
    const int tid = ty * 32 + tx;
    const int o0 = blockIdx.x * 32;
    const int b0 = blockIdx.y * 16;

    const float4* Wg = reinterpret_cast<const float4*>(We + o0 * IN);
    for (int idx = tid; idx < 32 * I4; idx += 256) {
        int o = idx / I4, i4 = idx - o * I4;
        We_s[i4 * 32 + o] = Wg[o * I4 + i4];
    }
    const float4* Hg = reinterpret_cast<const float4*>(h_in + b0 * IN);
    for (int idx = tid; idx < 16 * I4; idx += 256) {
        int b = idx / I4, i4 = idx - b * I4;
        h_s[b][i4] = Hg[b * I4 + i4];
    }
    __syncthreads();

    const float4* wc = &We_s[tx];
    const int bl = ty * 2;
    float accA = 0.f, accB = 0.f;
#pragma unroll 8
    for (int i4 = 0; i4 < I4; i4++) {
        float4 w  = wc[i4 * 32];
        float4 ha = h_s[bl][i4];
        float4 hb = h_s[bl + 1][i4];
        accA += w.x * ha.x + w.y * ha.y + w.z * ha.z + w.w * ha.w;
        accB += w.x * hb.x + w.y * hb.y + w.z * hb.z + w.w * hb.w;
    }
    float bb = bias[o0 + tx];
    out[(b0 + bl)     * OUT + o0 + tx] = accA + bb;
    out[(b0 + bl + 1) * OUT + o0 + tx] = accB + bb;
}

extern "C" void kernel_launch(void* const* d_in, const int* in_sizes, int n_in,
                              void* d_out, int out_size) {
    // Resolve input ordering at runtime (dict vs signature order).
    const float *x, *W0, *b0, *W1, *b1, *W2, *b2;
    const int *f0, *f1, *f2;
    x = (const float*)d_in[0];
    if (in_sizes[4] == 256) {
        // signature order: x, W0,b0, W1,b1, W2,b2, f0,f1,f2
        W0 = (const float*)d_in[1]; b0 = (const float*)d_in[2];
        W1 = (const float*)d_in[3]; b1 = (const float*)d_in[4];
        W2 = (const float*)d_in[5]; b2 = (const float*)d_in[6];
        f0 = (const int*)d_in[7];  f1 = (const int*)d_in[8];  f2 = (const int*)d_in[9];
    } else {
        // dict order: x, W0,b0,f0, W1,b1,f1, W2,b2,f2
        W0 = (const float*)d_in[1]; b0 = (const float*)d_in[2]; f0 = (const int*)d_in[3];
        W1 = (const float*)d_in[4]; b1 = (const float*)d_in[5]; f1 = (const int*)d_in[6];
        W2 = (const float*)d_in[7]; b2 = (const float*)d_in[8]; f2 = (const int*)d_in[9];
    }

    __half *dWe0h, *dWe1h;
    float *dWe2, *dh1, *dh2;
    cudaGetSymbolAddress((void**)&dWe0h, g_We0h);
    cudaGetSymbolAddress((void**)&dWe1h, g_We1h);
    cudaGetSymbolAddress((void**)&dWe2, g_We2);
    cudaGetSymbolAddress((void**)&dh1, g_h1);
    cudaGetSymbolAddress((void**)&dh2, g_h2);

    float* out = (float*)d_out;

    prep_we_kernel<<<256, 256>>>(W0, f0, W1, f1, W2, f2);

    dim3 blk(32, 8);
    // Layer 0: x[2048,256] -> h1[2048,256], f16x2 tanh
    layer_tanh_kernel<D0><<<dim3(D1 / 32, BATCH / 8), blk>>>(x, dWe0h, b0, dh1, D1);
    // Layer 1: h1 -> h2[2048,256], f16x2 tanh
    layer_tanh_kernel<D1><<<dim3(D2 / 32, BATCH / 8), blk>>>(dh1, dWe1h, b1, dh2, D2);
    // Layer 2: h2 -> out[2048,128], identity GEMM (register-tiled)
    layer_lin_kernel<<<dim3(D3 / 32, BATCH / 16), blk>>>(dh2, dWe2, b2, out, D3);
}

// round 6
// speedup vs baseline: 1.1421x; 1.1421x over previous
#include <cuda_runtime.h>
#include <cstdint>

#define BATCH 2048
#define D0 256
#define D1 256
#define D2 256
#define D3 128

// Scratch (device globals: allocation-free per harness rules)
__device__ float g_We0[D1 * D0];
__device__ float g_We1[D2 * D1];
__device__ float g_We2[D3 * D2];
__device__ float g_h1[BATCH * D1];
__device__ float g_h2[BATCH * D2];

__device__ __forceinline__ float tanh_fast(float x) {
    float y;
    asm("tanh.approx.f32 %0, %1;" : "=f"(y) : "f"(x));
    return y;
}

__device__ __forceinline__ float atom_apply(float w, int idx) {
    float v = w;                       // identity
    if (idx == 1)      v = sinf(w);
    else if (idx == 2) v = tanhf(w);
    else if (idx == 3) v = w * w;
    return v;
}

// Precompute effective weights We = atom(W, idx) for all three layers.
__global__ void prep_we_kernel(const float* __restrict__ W0, const int* __restrict__ f0,
                               const float* __restrict__ W1, const int* __restrict__ f1,
                               const float* __restrict__ W2, const int* __restrict__ f2) {
    const int n01 = D1 * D0;           // 65536
    const int n2  = D3 * D2;           // 32768
    const int stride = gridDim.x * blockDim.x;
    for (int t = blockIdx.x * blockDim.x + threadIdx.x; t < n01; t += stride) {
        g_We0[t] = atom_apply(W0[t], f0[t]);
        g_We1[t] = atom_apply(W1[t], f1[t]);
    }
    for (int t = blockIdx.x * blockDim.x + threadIdx.x; t < n2; t += stride) {
        g_We2[t] = atom_apply(W2[t], f2[t]);
    }
}

// Hidden layer: h_out[b,o] = sum_i tanh(h[b,i]*We[o,i]) + bias[o]
// MUFU-bound (tanh.approx.f32, 16 elem/cyc/SM). Block (32,8): tx->32 outputs,
// ty->8 batches. We tile transposed+padded in smem (conflict-free per-lane),
// h reads warp-uniform (broadcast).
template <int IN>
__global__ __launch_bounds__(256) void layer_tanh_kernel(
    const float* __restrict__ h_in,   // [BATCH, IN]
    const float* __restrict__ We,     // [OUT, IN]
    const float* __restrict__ bias,   // [OUT]
    float* __restrict__ h_out,        // [BATCH, OUT]
    int OUT) {
    __shared__ float We_s[IN][33];    // [i][o_local]
    __shared__ float h_s[8][IN];

    const int tx = threadIdx.x;
    const int ty = threadIdx.y;
    const int tid = ty * 32 + tx;
    const int o0 = blockIdx.x * 32;
    const int b0 = blockIdx.y * 8;

    // Stage We tile transposed (gmem coalesced over i; smem stride-33 conflict-free).
    for (int idx = tid; idx < 32 * IN; idx += 256) {
        int o = idx / IN;
        int i = idx - o * IN;
        We_s[i][o] = We[(o0 + o) * IN + i];
    }
    // Stage h tile, vectorized.
    const float4* Hg = reinterpret_cast<const float4*>(h_in + b0 * IN);
    float4* Hs = reinterpret_cast<float4*>(&h_s[0][0]);
    for (int idx = tid; idx < 8 * IN / 4; idx += 256) {
        Hs[idx] = Hg[idx];
    }
    __syncthreads();

    float acc0 = 0.f, acc1 = 0.f;
#pragma unroll 8
    for (int i = 0; i < IN; i += 2) {
        float z0 = h_s[ty][i]     * We_s[i][tx];
        float z1 = h_s[ty][i + 1] * We_s[i + 1][tx];
        acc0 += tanh_fast(z0);
        acc1 += tanh_fast(z1);
    }
    h_out[(b0 + ty) * OUT + o0 + tx] = acc0 + acc1 + bias[o0 + tx];
}

// Last layer (identity): fp32 GEMM, register tiled 2 outputs x 4 batches per
// thread (8 accs, 3 LDS-bytes/FMA -> FMA-bound). Tile 64o x 32b, k chunked by 64.
__global__ __launch_bounds__(256) void layer_lin_kernel(
    const float* __restrict__ h_in,     // [BATCH, 256]
    const float* __restrict__ We,       // [OUT, 256]
    const float* __restrict__ bias,     // [OUT]
    float* __restrict__ out,            // [BATCH, OUT]
    int OUT) {
    constexpr int IN = 256, KC = 64;
    __shared__ float W_s[KC][65];       // [k][o_local], padded
    __shared__ float h_s[32][KC + 1];   // [b_local][k], padded

    const int tx = threadIdx.x;         // 0..31
    const int ty = threadIdx.y;         // 0..7
    const int tid = ty * 32 + tx;
    const int o0 = blockIdx.x * 64;
    const int b0 = blockIdx.y * 32;

    // Thread computes outputs (tx, tx+32) x batches (ty*4 .. ty*4+3)
    const int bl = ty * 4;
    float acc[2][4];
#pragma unroll
    for (int a = 0; a < 2; a++)
#pragma unroll
        for (int b = 0; b < 4; b++) acc[a][b] = 0.f;

    for (int kc = 0; kc < IN; kc += KC) {
        // Stage W chunk: 64 o-rows x 64 k, transposed into W_s[k][o].
        for (int idx = tid; idx < 64 * KC; idx += 256) {
            int o = idx / KC;
            int k = idx - o * KC;
            W_s[k][o] = We[(o0 + o) * IN + kc + k];
        }
        // Stage h chunk: 32 batches x 64 k.
        for (int idx = tid; idx < 32 * KC; idx += 256) {
            int b = idx / KC;
            int k = idx - b * KC;
            h_s[b][k] = h_in[(b0 + b) * IN + kc + k];
        }
        __syncthreads();

#pragma unroll 8
        for (int k = 0; k < KC; k++) {
            float w0 = W_s[k][tx];        // lanes -> distinct banks
            float w1 = W_s[k][tx + 32];
            float hb0 = h_s[bl][k];       // warp-uniform broadcasts
            float hb1 = h_s[bl + 1][k];
            float hb2 = h_s[bl + 2][k];
            float hb3 = h_s[bl + 3][k];
            acc[0][0] += w0 * hb0;  acc[0][1] += w0 * hb1;
            acc[0][2] += w0 * hb2;  acc[0][3] += w0 * hb3;
            acc[1][0] += w1 * hb0;  acc[1][1] += w1 * hb1;
            acc[1][2] += w1 * hb2;  acc[1][3] += w1 * hb3;
        }
        __syncthreads();
    }

    float bb0 = bias[o0 + tx];
    float bb1 = bias[o0 + tx + 32];
#pragma unroll
    for (int b = 0; b < 4; b++) {
        out[(b0 + bl + b) * OUT + o0 + tx]      = acc[0][b] + bb0;
        out[(b0 + bl + b) * OUT + o0 + tx + 32] = acc[1][b] + bb1;
    }
}

extern "C" void kernel_launch(void* const* d_in, const int* in_sizes, int n_in,
                              void* d_out, int out_size) {
    // Resolve input ordering at runtime (dict vs signature order).
    const float *x, *W0, *b0, *W1, *b1, *W2, *b2;
    const int *f0, *f1, *f2;
    x = (const float*)d_in[0];
    if (in_sizes[4] == 256) {
        // signature order: x, W0,b0, W1,b1, W2,b2, f0,f1,f2
        W0 = (const float*)d_in[1]; b0 = (const float*)d_in[2];
        W1 = (const float*)d_in[3]; b1 = (const float*)d_in[4];
        W2 = (const float*)d_in[5]; b2 = (const float*)d_in[6];
        f0 = (const int*)d_in[7];  f1 = (const int*)d_in[8];  f2 = (const int*)d_in[9];
    } else {
        // dict order: x, W0,b0,f0, W1,b1,f1, W2,b2,f2
        W0 = (const float*)d_in[1]; b0 = (const float*)d_in[2]; f0 = (const int*)d_in[3];
        W1 = (const float*)d_in[4]; b1 = (const float*)d_in[5]; f1 = (const int*)d_in[6];
        W2 = (const float*)d_in[7]; b2 = (const float*)d_in[8]; f2 = (const int*)d_in[9];
    }

    float *dWe0, *dWe1, *dWe2, *dh1, *dh2;
    cudaGetSymbolAddress((void**)&dWe0, g_We0);
    cudaGetSymbolAddress((void**)&dWe1, g_We1);
    cudaGetSymbolAddress((void**)&dWe2, g_We2);
    cudaGetSymbolAddress((void**)&dh1, g_h1);
    cudaGetSymbolAddress((void**)&dh2, g_h2);

    float* out = (float*)d_out;

    prep_we_kernel<<<256, 256>>>(W0, f0, W1, f1, W2, f2);

    dim3 blk(32, 8);
    // Layer 0: x[2048,256] -> h1[2048,256], tanh (MUFU f32)
    layer_tanh_kernel<D0><<<dim3(D1 / 32, BATCH / 8), blk>>>(x, dWe0, b0, dh1, D1);
    // Layer 1: h1 -> h2[2048,256], tanh (MUFU f32)
    layer_tanh_kernel<D1><<<dim3(D2 / 32, BATCH / 8), blk>>>(dh1, dWe1, b1, dh2, D2);
    // Layer 2: h2 -> out[2048,128], identity GEMM (register tiled, FMA-bound)
    layer_lin_kernel<<<dim3(D3 / 64, BATCH / 32), blk>>>(dh2, dWe2, b2, out, D3);
}

// round 7
// speedup vs baseline: 1.1984x; 1.0493x over previous
#include <cuda_runtime.h>
#include <cstdint>

#define BATCH 2048
#define D0 256
#define D1 256
#define D2 256
#define D3 128

// Scratch (device globals: allocation-free per harness rules)
__device__ float g_We0[D1 * D0];
__device__ float g_We1[D2 * D1];
__device__ float g_We2[D3 * D2];
__device__ float g_h1[BATCH * D1];
__device__ float g_h2[BATCH * D2];

__device__ __forceinline__ float tanh_fast(float x) {
    float y;
    asm("tanh.approx.f32 %0, %1;" : "=f"(y) : "f"(x));
    return y;
}

__device__ __forceinline__ float atom_apply(float w, int idx) {
    float v = w;                       // identity
    if (idx == 1)      v = sinf(w);
    else if (idx == 2) v = tanhf(w);
    else if (idx == 3) v = w * w;
    return v;
}

// Precompute effective weights We = atom(W, idx) for all three layers.
__global__ void prep_we_kernel(const float* __restrict__ W0, const int* __restrict__ f0,
                               const float* __restrict__ W1, const int* __restrict__ f1,
                               const float* __restrict__ W2, const int* __restrict__ f2) {
    const int n01 = D1 * D0;           // 65536
    const int n2  = D3 * D2;           // 32768
    const int stride = gridDim.x * blockDim.x;
    for (int t = blockIdx.x * blockDim.x + threadIdx.x; t < n01; t += stride) {
        g_We0[t] = atom_apply(W0[t], f0[t]);
        g_We1[t] = atom_apply(W1[t], f1[t]);
    }
    for (int t = blockIdx.x * blockDim.x + threadIdx.x; t < n2; t += stride) {
        g_We2[t] = atom_apply(W2[t], f2[t]);
    }
}

// Hidden layer: h_out[b,o] = sum_i tanh(h[b,i]*We[o,i]) + bias[o]
// MUFU-bound (tanh.approx.f32, 16 elem/cyc/SM) — measured at floor; unchanged.
template <int IN>
__global__ __launch_bounds__(256) void layer_tanh_kernel(
    const float* __restrict__ h_in,   // [BATCH, IN]
    const float* __restrict__ We,     // [OUT, IN]
    const float* __restrict__ bias,   // [OUT]
    float* __restrict__ h_out,        // [BATCH, OUT]
    int OUT) {
    __shared__ float We_s[IN][33];    // [i][o_local]
    __shared__ float h_s[8][IN];

    const int tx = threadIdx.x;
    const int ty = threadIdx.y;
    const int tid = ty * 32 + tx;
    const int o0 = blockIdx.x * 32;
    const int b0 = blockIdx.y * 8;

    for (int idx = tid; idx < 32 * IN; idx += 256) {
        int o = idx / IN;
        int i = idx - o * IN;
        We_s[i][o] = We[(o0 + o) * IN + i];
    }
    const float4* Hg = reinterpret_cast<const float4*>(h_in + b0 * IN);
    float4* Hs = reinterpret_cast<float4*>(&h_s[0][0]);
    for (int idx = tid; idx < 8 * IN / 4; idx += 256) {
        Hs[idx] = Hg[idx];
    }
    __syncthreads();

    float acc0 = 0.f, acc1 = 0.f;
#pragma unroll 8
    for (int i = 0; i < IN; i += 2) {
        float z0 = h_s[ty][i]     * We_s[i][tx];
        float z1 = h_s[ty][i + 1] * We_s[i + 1][tx];
        acc0 += tanh_fast(z0);
        acc1 += tanh_fast(z1);
    }
    h_out[(b0 + ty) * OUT + o0 + tx] = acc0 + acc1 + bias[o0 + tx];
}

// Last layer (identity): fp32 GEMM. Tile 32o x 32b -> grid 256 CTAs (~2/SM).
// Thread: 1 output x 4 batches, float4 over k: per 4k = 1 LDS.128 (W) +
// 4 LDS.128 (h, warp-uniform) + 16 FFMA. 4 independent acc chains.
__global__ __launch_bounds__(256) void layer_lin_kernel(
    const float* __restrict__ h_in,     // [BATCH, 256]
    const float* __restrict__ We,       // [128, 256]
    const float* __restrict__ bias,     // [128]
    float* __restrict__ out) {          // [BATCH, 128]
    constexpr int IN = 256, KC = 128, OUT = D3;
    __shared__ float W_s[32][KC + 4];   // [o_local][k], row stride 132 (16B-aligned, conflict-free)
    __shared__ float h_s[32][KC + 4];   // [b_local][k]

    const int tx = threadIdx.x;         // 0..31 -> output
    const int ty = threadIdx.y;         // 0..7  -> batch group
    const int tid = ty * 32 + tx;
    const int o0 = blockIdx.x * 32;
    const int b0 = blockIdx.y * 32;
    const int bl = ty * 4;

    float acc0 = 0.f, acc1 = 0.f, acc2 = 0.f, acc3 = 0.f;

    for (int kc = 0; kc < IN; kc += KC) {
        // Stage W chunk: 32 rows x 128 k, float4 coalesced (4 float4 per thread).
        for (int idx = tid; idx < 32 * (KC / 4); idx += 256) {
            int o = idx / (KC / 4);
            int k4 = idx - o * (KC / 4);
            float4 v = *reinterpret_cast<const float4*>(&We[(o0 + o) * IN + kc + k4 * 4]);
            *reinterpret_cast<float4*>(&W_s[o][k4 * 4]) = v;
        }
        // Stage h chunk: 32 batches x 128 k.
        for (int idx = tid; idx < 32 * (KC / 4); idx += 256) {
            int b = idx / (KC / 4);
            int k4 = idx - b * (KC / 4);
            float4 v = *reinterpret_cast<const float4*>(&h_in[(b0 + b) * IN + kc + k4 * 4]);
            *reinterpret_cast<float4*>(&h_s[b][k4 * 4]) = v;
        }
        __syncthreads();

#pragma unroll 8
        for (int k = 0; k < KC; k += 4) {
            float4 w  = *reinterpret_cast<float4*>(&W_s[tx][k]);
            float4 h0 = *reinterpret_cast<float4*>(&h_s[bl][k]);
            float4 h1 = *reinterpret_cast<float4*>(&h_s[bl + 1][k]);
            float4 h2 = *reinterpret_cast<float4*>(&h_s[bl + 2][k]);
            float4 h3 = *reinterpret_cast<float4*>(&h_s[bl + 3][k]);
            acc0 += w.x * h0.x + w.y * h0.y + w.z * h0.z + w.w * h0.w;
            acc1 += w.x * h1.x + w.y * h1.y + w.z * h1.z + w.w * h1.w;
            acc2 += w.x * h2.x + w.y * h2.y + w.z * h2.z + w.w * h2.w;
            acc3 += w.x * h3.x + w.y * h3.y + w.z * h3.z + w.w * h3.w;
        }
        __syncthreads();
    }

    float bb = bias[o0 + tx];
    out[(b0 + bl)     * OUT + o0 + tx] = acc0 + bb;
    out[(b0 + bl + 1) * OUT + o0 + tx] = acc1 + bb;
    out[(b0 + bl + 2) * OUT + o0 + tx] = acc2 + bb;
    out[(b0 + bl + 3) * OUT + o0 + tx] = acc3 + bb;
}

extern "C" void kernel_launch(void* const* d_in, const int* in_sizes, int n_in,
                              void* d_out, int out_size) {
    // Resolve input ordering at runtime (dict vs signature order).
    const float *x, *W0, *b0, *W1, *b1, *W2, *b2;
    const int *f0, *f1, *f2;
    x = (const float*)d_in[0];
    if (in_sizes[4] == 256) {
        // signature order: x, W0,b0, W1,b1, W2,b2, f0,f1,f2
        W0 = (const float*)d_in[1]; b0 = (const float*)d_in[2];
        W1 = (const float*)d_in[3]; b1 = (const float*)d_in[4];
        W2 = (const float*)d_in[5]; b2 = (const float*)d_in[6];
        f0 = (const int*)d_in[7];  f1 = (const int*)d_in[8];  f2 = (const int*)d_in[9];
    } else {
        // dict order: x, W0,b0,f0, W1,b1,f1, W2,b2,f2
        W0 = (const float*)d_in[1]; b0 = (const float*)d_in[2]; f0 = (const int*)d_in[3];
        W1 = (const float*)d_in[4]; b1 = (const float*)d_in[5]; f1 = (const int*)d_in[6];
        W2 = (const float*)d_in[7]; b2 = (const float*)d_in[8]; f2 = (const int*)d_in[9];
    }

    float *dWe0, *dWe1, *dWe2, *dh1, *dh2;
    cudaGetSymbolAddress((void**)&dWe0, g_We0);
    cudaGetSymbolAddress((void**)&dWe1, g_We1);
    cudaGetSymbolAddress((void**)&dWe2, g_We2);
    cudaGetSymbolAddress((void**)&dh1, g_h1);
    cudaGetSymbolAddress((void**)&dh2, g_h2);

    float* out = (float*)d_out;

    prep_we_kernel<<<256, 256>>>(W0, f0, W1, f1, W2, f2);

    dim3 blk(32, 8);
    // Layer 0: x[2048,256] -> h1[2048,256], tanh (MUFU f32)
    layer_tanh_kernel<D0><<<dim3(D1 / 32, BATCH / 8), blk>>>(x, dWe0, b0, dh1, D1);
    // Layer 1: h1 -> h2[2048,256], tanh (MUFU f32)
    layer_tanh_kernel<D1><<<dim3(D2 / 32, BATCH / 8), blk>>>(dh1, dWe1, b1, dh2, D2);
    // Layer 2: h2 -> out[2048,128], identity GEMM (32o x 32b tiles, 256 CTAs)
    layer_lin_kernel<<<dim3(D3 / 32, BATCH / 32), blk>>>(dh2, dWe2, b2, out);
}